// round 10
// baseline (speedup 1.0000x reference)
#include <cuda_runtime.h>
#include <math.h>
#include <stdint.h>

#define BATCH   2
#define T_SEQ   2048
#define CDIM    1024
#define HEADS   16
#define DHEAD   64
#define C3      3072
#define MROWS   4096

__device__ float g_qkv[(size_t)MROWS * C3];   // 48 MB
__device__ float g_y  [(size_t)MROWS * CDIM]; // 16 MB

// ---- tf32 helpers ----------------------------------------------------------
__device__ __forceinline__ uint32_t f2tf32(float x) {
    uint32_t u; asm("cvt.rna.tf32.f32 %0, %1;" : "=r"(u) : "f"(x)); return u;
}
__device__ __forceinline__ void mma_tf32(float* d, const uint32_t* a, const uint32_t* b) {
    asm volatile("mma.sync.aligned.m16n8k8.row.col.f32.tf32.tf32.f32 "
        "{%0,%1,%2,%3}, {%4,%5,%6,%7}, {%8,%9}, {%0,%1,%2,%3};"
        : "+f"(d[0]), "+f"(d[1]), "+f"(d[2]), "+f"(d[3])
        : "r"(a[0]), "r"(a[1]), "r"(a[2]), "r"(a[3]), "r"(b[0]), "r"(b[1]));
}

// ---------------------------------------------------------------------------
// NT GEMM on tensor cores: C[M,N] = A[M,K] * B[N,K]^T via 3xTF32 mma.sync.
// Block 128x128, 512 thr (16 warps, 4x4 grid of 32x32 warp tiles), BK=16,
// double-buffered SMEM in FRAGMENT-MAJOR layout:
//   A frag (m16k8 tile): [tile][lane][4 slots]  -> one LDS.128 per frag
//   B frag (k8n8 tile) : [tile][lane][2 slots]  -> one LDS.64 per frag
// hi/lo tf32 split computed during staging (cvt.rna.tf32).
// ---------------------------------------------------------------------------
#define GBK 16
// per-buffer float offsets inside dynamic smem (8192 floats per buffer)
//   Ahi 0..2047 | Alo 2048.. | Bhi 4096.. | Blo 6144..
__global__ void __launch_bounds__(512, 1)
gemm_tf32_kernel(const float* __restrict__ A,
                 const float* __restrict__ B,
                 float* __restrict__ C,
                 int M, int N, int K)
{
    extern __shared__ __align__(16) float gsm[];

    const int t    = threadIdx.x;
    const int lane = t & 31;
    const int w    = t >> 5;
    const int wm   = w >> 2;       // 0..3  (m tile of 32)
    const int wn   = w & 3;        // 0..3  (n tile of 32)
    const int grp  = lane >> 2;    // 0..7
    const int qt   = lane & 3;     // 0..3
    const int m0   = blockIdx.y * 128;
    const int n0   = blockIdx.x * 128;

    // staging coords: thread covers row (t>>2) of both A and B tiles, cols aq4*4..+3
    const int am  = t >> 2;        // 0..127
    const int aq4 = t & 3;         // 0..3

    float acc[2][4][4];
    #pragma unroll
    for (int mt = 0; mt < 2; mt++)
        #pragma unroll
        for (int nt = 0; nt < 4; nt++)
            #pragma unroll
            for (int i = 0; i < 4; i++) acc[mt][nt][i] = 0.f;

    const float* Arow = A + (size_t)(m0 + am) * K + aq4 * 4;
    const float* Brow = B + (size_t)(n0 + am) * K + aq4 * 4;

    // stage one (va, vb) pair into buffer `buf`
    auto stage = [&](float4 va, float4 vb, int buf) {
        float* Ahi = gsm + buf * 8192;
        float* Alo = Ahi + 2048;
        float* Bhi = Ahi + 4096;
        float* Blo = Ahi + 6144;
        float av[4] = { va.x, va.y, va.z, va.w };
        float bv[4] = { vb.x, vb.y, vb.z, vb.w };
        const int mt = am >> 4, r  = am & 15;   // A: m16 tile, row-in-tile
        const int ntb = am >> 3, nl = am & 7;   // B: n8 tile, n-in-tile
        #pragma unroll
        for (int j = 0; j < 4; j++) {
            const int cf = aq4 * 4 + j;         // 0..15
            const int kg = cf >> 3, c = cf & 7; // k8 group, col-in-group
            // A fragment slot: a0:(r<8,c<4) a1:(r>=8,c<4) a2:(r<8,c>=4) a3:(r>=8,c>=4)
            const int laneA = ((r & 7) << 2) + (c & 3);
            const int slotA = ((r >> 3) & 1) + ((c & 4) >> 1);
            const int ia = ((mt * 2 + kg) * 32 + laneA) * 4 + slotA;
            const uint32_t ha = f2tf32(av[j]);
            Ahi[ia] = __uint_as_float(ha);
            Alo[ia] = __uint_as_float(f2tf32(av[j] - __uint_as_float(ha)));
            // B fragment slot: b0:(c<4) b1:(c>=4); lane = n*4 + c%4
            const int laneB = (nl << 2) + (c & 3);
            const int slotB = (c & 4) >> 2;
            const int ib = ((ntb * 2 + kg) * 32 + laneB) * 2 + slotB;
            const uint32_t hb = f2tf32(bv[j]);
            Bhi[ib] = __uint_as_float(hb);
            Blo[ib] = __uint_as_float(f2tf32(bv[j] - __uint_as_float(hb)));
        }
    };

    float4 va = *(const float4*)Arow;
    float4 vb = *(const float4*)Brow;
    stage(va, vb, 0);
    __syncthreads();

    const int nch = K / GBK;   // 64
    for (int ch = 0; ch < nch; ch++) {
        const bool has = (ch + 1 < nch);
        if (has) {
            va = *(const float4*)(Arow + (ch + 1) * GBK);
            vb = *(const float4*)(Brow + (ch + 1) * GBK);
        }

        const float* Ah = gsm + (ch & 1) * 8192;   // Ahi; Alo at +2048
        const float* Bh = Ah + 4096;               // Bhi; Blo at +2048
        #pragma unroll
        for (int kg = 0; kg < 2; kg++) {
            uint4 ahr[2], alr[2];
            #pragma unroll
            for (int mt = 0; mt < 2; mt++) {
                const int mtg = wm * 2 + mt;
                ahr[mt] = *(const uint4*)&Ah[        ((mtg * 2 + kg) * 32 + lane) * 4];
                alr[mt] = *(const uint4*)&Ah[2048 +  ((mtg * 2 + kg) * 32 + lane) * 4];
            }
            #pragma unroll
            for (int nt = 0; nt < 4; nt++) {
                const int ntg = wn * 4 + nt;
                uint2 bhr = *(const uint2*)&Bh[       ((ntg * 2 + kg) * 32 + lane) * 2];
                uint2 blr = *(const uint2*)&Bh[2048 + ((ntg * 2 + kg) * 32 + lane) * 2];
                #pragma unroll
                for (int mt = 0; mt < 2; mt++) {
                    mma_tf32(acc[mt][nt], (const uint32_t*)&ahr[mt], (const uint32_t*)&bhr);
                    mma_tf32(acc[mt][nt], (const uint32_t*)&alr[mt], (const uint32_t*)&bhr);
                    mma_tf32(acc[mt][nt], (const uint32_t*)&ahr[mt], (const uint32_t*)&blr);
                }
            }
        }
        __syncthreads();
        if (has) {
            stage(va, vb, (ch + 1) & 1);
            __syncthreads();
        }
    }

    // epilogue: c0:(grp, 2qt) c1:(grp, 2qt+1) c2:(grp+8, 2qt) c3:(grp+8, 2qt+1)
    #pragma unroll
    for (int mt = 0; mt < 2; mt++) {
        #pragma unroll
        for (int nt = 0; nt < 4; nt++) {
            const int row = m0 + wm * 32 + mt * 16 + grp;
            const int col = n0 + wn * 32 + nt * 8 + qt * 2;
            *(float2*)&C[(size_t)row * N + col]       = make_float2(acc[mt][nt][0], acc[mt][nt][1]);
            *(float2*)&C[(size_t)(row + 8) * N + col] = make_float2(acc[mt][nt][2], acc[mt][nt][3]);
        }
    }
}

// ---------------------------------------------------------------------------
// Penalized attention (unchanged from the passing R9 version).
// softmax(P - Z) == softmax(P[k] + prefix_excl_sigmoid(k)).
//  - analytic softmax shift m = rtot + 8 (rtot cancels; no max reduce)
//  - lane owns adjacent keys (2*lane, 2*lane+1) via permuted K rows
//  - 51.7 KB smem, 4 CTAs/SM; reversed block order (longest first)
// ---------------------------------------------------------------------------
#define ATTN_SMEM_FLOATS (4352 + 4352 + 2176 + 2048)

__global__ void __launch_bounds__(256, 4)
attn_kernel(const float* __restrict__ qkv, float* __restrict__ yout)
{
    extern __shared__ __align__(16) float sm[];
    float* Ksh = sm;                 // [64][68], permuted rows
    float* Vsh = sm + 4352;          // [64][68], natural rows
    float* qsh = sm + 8704;          // [32][68]
    float* esh = sm + 10880;         // [8][4][64]

    const int b     = blockIdx.z;
    const int h     = blockIdx.y;
    const int qbase = (int)(gridDim.x - 1 - blockIdx.x) * 32;  // longest first
    const int w     = threadIdx.x >> 5;
    const int lane  = threadIdx.x & 31;
    const int d0    = 2 * lane;
    const float scale = 0.125f;

    #pragma unroll
    for (int i = 0; i < 2; i++) {
        int idx = threadIdx.x + i * 256;
        int qr = idx >> 4, c4 = idx & 15;
        const float* qptr = qkv + (size_t)(b * T_SEQ + qbase + qr) * C3 + h * DHEAD + c4 * 4;
        *(float4*)&qsh[qr * 68 + c4 * 4] = *(const float4*)qptr;
    }

    const float* Kbase = qkv + (size_t)(b * T_SEQ) * C3 + CDIM     + h * DHEAD;
    const float* Vbase = qkv + (size_t)(b * T_SEQ) * C3 + 2 * CDIM + h * DHEAD;
    const int ntiles = (qbase >> 6) + 1;

    float denl[4], y0[4], y1[4];
    #pragma unroll
    for (int g = 0; g < 4; g++) { denl[g] = 0.f; y0[g] = 0.f; y1[g] = 0.f; }

    for (int tile = 0; tile < ntiles; tile++) {
        const int kt0 = tile << 6;
        __syncthreads();
        #pragma unroll
        for (int i = 0; i < 4; i++) {
            int idx = threadIdx.x + i * 256;
            int r = idx >> 4, c4 = idx & 15;
            size_t gofs = (size_t)(kt0 + r) * C3 + c4 * 4;
            int prow = (r & 1) ? (32 + (r >> 1)) : (r >> 1);
            *(float4*)&Ksh[prow * 68 + c4 * 4] = *(const float4*)&Kbase[gofs];
            *(float4*)&Vsh[r    * 68 + c4 * 4] = *(const float4*)&Vbase[gofs];
        }
        __syncthreads();

        float p0[4] = {0.f, 0.f, 0.f, 0.f}, p1[4] = {0.f, 0.f, 0.f, 0.f};
        {
            const float4* K0 = (const float4*)&Ksh[lane * 68];
            const float4* K1 = (const float4*)&Ksh[(lane + 32) * 68];
            #pragma unroll
            for (int d4 = 0; d4 < 16; d4++) {
                float4 k0 = K0[d4], k1 = K1[d4];
                #pragma unroll
                for (int g = 0; g < 4; g++) {
                    float4 qv = *(const float4*)&qsh[(w * 4 + g) * 68 + d4 * 4];
                    p0[g] += qv.x * k0.x + qv.y * k0.y + qv.z * k0.z + qv.w * k0.w;
                    p1[g] += qv.x * k1.x + qv.y * k1.y + qv.z * k1.z + qv.w * k1.w;
                }
            }
        }

        float alpha_g[4];
        #pragma unroll
        for (int g = 0; g < 4; g++) {
            const int q    = qbase + w * 4 + g;
            const int key0 = kt0 + 2 * lane;
            const bool v0 = (key0 <= q), v1 = (key0 + 1 <= q);
            const float P0 = p0[g] * scale;
            const float P1 = p1[g] * scale;
            const float s0 = v0 ? __fdividef(1.0f, 1.0f + __expf(-P0)) : 0.f;
            const float s1 = v1 ? __fdividef(1.0f, 1.0f + __expf(-P1)) : 0.f;

            float sp = s0 + s1;
            float sc = sp;
            #pragma unroll
            for (int off = 1; off < 32; off <<= 1) {
                float tv = __shfl_up_sync(0xffffffffu, sc, off);
                if (lane >= off) sc += tv;
            }
            const float tot  = __shfl_sync(0xffffffffu, sc, 31);
            const float excl = sc - sp;

            const float c0 = excl - tot - 8.0f;
            const float e0 = v0 ? __expf(P0 + c0)      : 0.f;
            const float e1 = v1 ? __expf(P1 + c0 + s0) : 0.f;
            const float al = __expf(-tot);
            denl[g] = denl[g] * al + e0 + e1;
            alpha_g[g] = al;
            *(float2*)&esh[(w * 4 + g) * 64 + 2 * lane] = make_float2(e0, e1);
        }
        __syncwarp();

        #pragma unroll
        for (int g = 0; g < 4; g++) { y0[g] *= alpha_g[g]; y1[g] *= alpha_g[g]; }
        #pragma unroll
        for (int k4 = 0; k4 < 16; k4++) {
            float2 v0 = *(const float2*)&Vsh[(k4 * 4 + 0) * 68 + d0];
            float2 v1 = *(const float2*)&Vsh[(k4 * 4 + 1) * 68 + d0];
            float2 v2 = *(const float2*)&Vsh[(k4 * 4 + 2) * 68 + d0];
            float2 v3 = *(const float2*)&Vsh[(k4 * 4 + 3) * 68 + d0];
            #pragma unroll
            for (int g = 0; g < 4; g++) {
                float4 ev = *(const float4*)&esh[(w * 4 + g) * 64 + k4 * 4];
                y0[g] += ev.x * v0.x + ev.y * v1.x + ev.z * v2.x + ev.w * v3.x;
                y1[g] += ev.x * v0.y + ev.y * v1.y + ev.z * v2.y + ev.w * v3.y;
            }
        }
        __syncwarp();
    }

    #pragma unroll
    for (int g = 0; g < 4; g++) {
        float dsum = denl[g];
        #pragma unroll
        for (int off = 16; off; off >>= 1)
            dsum += __shfl_xor_sync(0xffffffffu, dsum, off);
        const float inv = 1.0f / dsum;
        const int q = qbase + w * 4 + g;
        float* yp = yout + (size_t)(b * T_SEQ + q) * CDIM + h * DHEAD + d0;
        *(float2*)yp = make_float2(y0[g] * inv, y1[g] * inv);
    }
}

// ---------------------------------------------------------------------------
extern "C" void kernel_launch(void* const* d_in, const int* in_sizes, int n_in,
                              void* d_out, int out_size)
{
    const float* x = nullptr; const float* Wa = nullptr; const float* Wp = nullptr;
    for (int i = 0; i < n_in; i++) {
        if (in_sizes[i] == BATCH * T_SEQ * CDIM)  x  = (const float*)d_in[i];
        else if (in_sizes[i] == C3 * CDIM)        Wa = (const float*)d_in[i];
        else if (in_sizes[i] == CDIM * CDIM)      Wp = (const float*)d_in[i];
    }
    float* out = (float*)d_out;

    void* qkv_p = nullptr; void* y_p = nullptr;
    cudaGetSymbolAddress(&qkv_p, g_qkv);
    cudaGetSymbolAddress(&y_p,   g_y);
    float* qkv = (float*)qkv_p;
    float* y   = (float*)y_p;

    const int GEMM_SMEM = 2 * 8192 * 4;           // 65,536 B
    const int ATTN_SMEM = ATTN_SMEM_FLOATS * 4;   // 51,712 B
    cudaFuncSetAttribute(gemm_tf32_kernel, cudaFuncAttributeMaxDynamicSharedMemorySize, GEMM_SMEM);
    cudaFuncSetAttribute(attn_kernel,      cudaFuncAttributeMaxDynamicSharedMemorySize, ATTN_SMEM);

    {   // qkv = x @ W_attn^T
        dim3 grid(C3 / 128, MROWS / 128);
        gemm_tf32_kernel<<<grid, 512, GEMM_SMEM>>>(x, Wa, qkv, MROWS, C3, CDIM);
    }
    {   // penalized attention
        dim3 grid(T_SEQ / 32, HEADS, BATCH);
        attn_kernel<<<grid, 256, ATTN_SMEM>>>(qkv, y);
    }
    {   // out = y @ W_proj^T
        dim3 grid(CDIM / 128, MROWS / 128);
        gemm_tf32_kernel<<<grid, 512, GEMM_SMEM>>>(y, Wp, out, MROWS, CDIM, CDIM);
    }
}

// round 11
// speedup vs baseline: 1.3314x; 1.3314x over previous
#include <cuda_runtime.h>
#include <math.h>
#include <stdint.h>

#define BATCH   2
#define T_SEQ   2048
#define CDIM    1024
#define HEADS   16
#define DHEAD   64
#define C3      3072
#define MROWS   4096

__device__ float g_qkv[(size_t)MROWS * C3];   // 48 MB
__device__ float g_y  [(size_t)MROWS * CDIM]; // 16 MB

// ---- tf32 helpers ----------------------------------------------------------
__device__ __forceinline__ uint32_t f2tf32(float x) {
    uint32_t u; asm("cvt.rna.tf32.f32 %0, %1;" : "=r"(u) : "f"(x)); return u;
}
__device__ __forceinline__ void mma_tf32(float* d, const uint32_t* a, const uint32_t* b) {
    asm volatile("mma.sync.aligned.m16n8k8.row.col.f32.tf32.tf32.f32 "
        "{%0,%1,%2,%3}, {%4,%5,%6,%7}, {%8,%9}, {%0,%1,%2,%3};"
        : "+f"(d[0]), "+f"(d[1]), "+f"(d[2]), "+f"(d[3])
        : "r"(a[0]), "r"(a[1]), "r"(a[2]), "r"(a[3]), "r"(b[0]), "r"(b[1]));
}

// ---------------------------------------------------------------------------
// NT GEMM on tensor cores: C[M,N] = A[M,K] * B[N,K]^T via 3xTF32 mma.sync.
// Block 128x128, 256 thr (8 warps, 2x4 grid of 64x32 warp tiles), BK=16,
// double-buffered. SMEM "panel" layout addr(row,k) = (k/4)*520 + row*4 + k%4:
//   - staging: STS.128, conflict-free per quarter-warp phase
//   - fragment loads: LDS.32 with bank == lane (conflict-free, A and B)
// hi/lo tf32 split done once in staging (amortized over consuming warps).
// ---------------------------------------------------------------------------
#define GS_PANEL 520                    // floats per k-panel (128*4 + 8 pad)
#define GS_A_HI  0
#define GS_A_LO  (4 * GS_PANEL)        // 2080
#define GS_B_HI  (8 * GS_PANEL)        // 4160
#define GS_B_LO  (12 * GS_PANEL)       // 6240
#define GS_BUF   (16 * GS_PANEL)       // 8320 floats per buffer

__global__ void __launch_bounds__(256, 2)
gemm_tf32_kernel(const float* __restrict__ A,
                 const float* __restrict__ B,
                 float* __restrict__ C,
                 int M, int N, int K)
{
    extern __shared__ __align__(16) float gsm[];

    const int t    = threadIdx.x;
    const int lane = t & 31;
    const int w    = t >> 5;
    const int wm   = w >> 2;       // 0..1  (m tile of 64)
    const int wn   = w & 3;        // 0..3  (n tile of 32)
    const int grp  = lane >> 2;    // 0..7
    const int qt   = lane & 3;     // 0..3
    const int m0   = blockIdx.y * 128;
    const int n0   = blockIdx.x * 128;

    // staging coords: thread covers rows srow, srow+64; k-cols sc4*4..+3
    const int srow = t >> 2;       // 0..63
    const int sc4  = t & 3;        // 0..3

    float acc[4][4][4];
    #pragma unroll
    for (int mt = 0; mt < 4; mt++)
        #pragma unroll
        for (int nt = 0; nt < 4; nt++)
            #pragma unroll
            for (int i = 0; i < 4; i++) acc[mt][nt][i] = 0.f;

    const float* Ap0 = A + (size_t)(m0 + srow)      * K + sc4 * 4;
    const float* Ap1 = A + (size_t)(m0 + srow + 64) * K + sc4 * 4;
    const float* Bp0 = B + (size_t)(n0 + srow)      * K + sc4 * 4;
    const float* Bp1 = B + (size_t)(n0 + srow + 64) * K + sc4 * 4;

    // stage 4 float4s (A rows srow/srow+64, B rows srow/srow+64) into buffer
    auto stage = [&](float4 va0, float4 va1, float4 vb0, float4 vb1, int buf) {
        float* bb = gsm + buf * GS_BUF;
        const int off0 = sc4 * GS_PANEL + srow * 4;   // row srow
        const int off1 = off0 + 256;                  // row srow+64
        float4 h, l;
        #define SPLIT_STORE(vec, hoff, loff)                                   \
            { uint32_t hx = f2tf32((vec).x), hy = f2tf32((vec).y),             \
                       hz = f2tf32((vec).z), hw = f2tf32((vec).w);             \
              h = make_float4(__uint_as_float(hx), __uint_as_float(hy),        \
                              __uint_as_float(hz), __uint_as_float(hw));       \
              l = make_float4(                                                  \
                  __uint_as_float(f2tf32((vec).x - __uint_as_float(hx))),      \
                  __uint_as_float(f2tf32((vec).y - __uint_as_float(hy))),      \
                  __uint_as_float(f2tf32((vec).z - __uint_as_float(hz))),      \
                  __uint_as_float(f2tf32((vec).w - __uint_as_float(hw))));     \
              *(float4*)&bb[hoff] = h; *(float4*)&bb[loff] = l; }
        SPLIT_STORE(va0, GS_A_HI + off0, GS_A_LO + off0);
        SPLIT_STORE(va1, GS_A_HI + off1, GS_A_LO + off1);
        SPLIT_STORE(vb0, GS_B_HI + off0, GS_B_LO + off0);
        SPLIT_STORE(vb1, GS_B_HI + off1, GS_B_LO + off1);
        #undef SPLIT_STORE
    };

    float4 va0 = *(const float4*)Ap0, va1 = *(const float4*)Ap1;
    float4 vb0 = *(const float4*)Bp0, vb1 = *(const float4*)Bp1;
    stage(va0, va1, vb0, vb1, 0);
    __syncthreads();

    // fragment base offsets (lane-resolved, bank == lane)
    const int abase = (wm * 64 + grp) * 4 + qt;   // + mt*64 ; +32 row+8 ; +PANEL col+4
    const int bbase = (wn * 32 + grp) * 4 + qt;   // + nt*32 ; +PANEL k+4

    const int nch = K / 16;   // 64
    for (int ch = 0; ch < nch; ch++) {
        const bool has = (ch + 1 < nch);
        if (has) {
            va0 = *(const float4*)(Ap0 + (ch + 1) * 16);
            va1 = *(const float4*)(Ap1 + (ch + 1) * 16);
            vb0 = *(const float4*)(Bp0 + (ch + 1) * 16);
            vb1 = *(const float4*)(Bp1 + (ch + 1) * 16);
        }

        const float* Sb = gsm + (ch & 1) * GS_BUF;
        #pragma unroll
        for (int kg = 0; kg < 2; kg++) {
            const int pk = kg * 2 * GS_PANEL;
            // B fragments (hi/lo) for 4 n-tiles
            uint32_t bh[4][2], bl[4][2];
            #pragma unroll
            for (int nt = 0; nt < 4; nt++) {
                const int o = pk + bbase + nt * 32;
                bh[nt][0] = __float_as_uint(Sb[GS_B_HI + o]);
                bh[nt][1] = __float_as_uint(Sb[GS_B_HI + o + GS_PANEL]);
                bl[nt][0] = __float_as_uint(Sb[GS_B_LO + o]);
                bl[nt][1] = __float_as_uint(Sb[GS_B_LO + o + GS_PANEL]);
            }
            #pragma unroll
            for (int mt = 0; mt < 4; mt++) {
                const int o = pk + abase + mt * 64;
                uint32_t ah[4], al[4];
                ah[0] = __float_as_uint(Sb[GS_A_HI + o]);
                ah[1] = __float_as_uint(Sb[GS_A_HI + o + 32]);
                ah[2] = __float_as_uint(Sb[GS_A_HI + o + GS_PANEL]);
                ah[3] = __float_as_uint(Sb[GS_A_HI + o + GS_PANEL + 32]);
                al[0] = __float_as_uint(Sb[GS_A_LO + o]);
                al[1] = __float_as_uint(Sb[GS_A_LO + o + 32]);
                al[2] = __float_as_uint(Sb[GS_A_LO + o + GS_PANEL]);
                al[3] = __float_as_uint(Sb[GS_A_LO + o + GS_PANEL + 32]);
                #pragma unroll
                for (int nt = 0; nt < 4; nt++) {
                    mma_tf32(acc[mt][nt], ah, bh[nt]);
                    mma_tf32(acc[mt][nt], al, bh[nt]);
                    mma_tf32(acc[mt][nt], ah, bl[nt]);
                }
            }
        }
        __syncthreads();
        if (has) {
            stage(va0, va1, vb0, vb1, (ch + 1) & 1);
            __syncthreads();
        }
    }

    // epilogue: c0:(grp, 2qt) c1:(grp, 2qt+1) c2:(grp+8, 2qt) c3:(grp+8, 2qt+1)
    #pragma unroll
    for (int mt = 0; mt < 4; mt++) {
        #pragma unroll
        for (int nt = 0; nt < 4; nt++) {
            const int row = m0 + wm * 64 + mt * 16 + grp;
            const int col = n0 + wn * 32 + nt * 8 + qt * 2;
            *(float2*)&C[(size_t)row * N + col]       = make_float2(acc[mt][nt][0], acc[mt][nt][1]);
            *(float2*)&C[(size_t)(row + 8) * N + col] = make_float2(acc[mt][nt][2], acc[mt][nt][3]);
        }
    }
}

// ---------------------------------------------------------------------------
// Penalized attention (unchanged from the passing R9 version).
// softmax(P - Z) == softmax(P[k] + prefix_excl_sigmoid(k)).
//  - analytic softmax shift m = rtot + 8 (rtot cancels; no max reduce)
//  - lane owns adjacent keys (2*lane, 2*lane+1) via permuted K rows
//  - 51.7 KB smem, 4 CTAs/SM; reversed block order (longest first)
// ---------------------------------------------------------------------------
#define ATTN_SMEM_FLOATS (4352 + 4352 + 2176 + 2048)

__global__ void __launch_bounds__(256, 4)
attn_kernel(const float* __restrict__ qkv, float* __restrict__ yout)
{
    extern __shared__ __align__(16) float sm[];
    float* Ksh = sm;                 // [64][68], permuted rows
    float* Vsh = sm + 4352;          // [64][68], natural rows
    float* qsh = sm + 8704;          // [32][68]
    float* esh = sm + 10880;         // [8][4][64]

    const int b     = blockIdx.z;
    const int h     = blockIdx.y;
    const int qbase = (int)(gridDim.x - 1 - blockIdx.x) * 32;  // longest first
    const int w     = threadIdx.x >> 5;
    const int lane  = threadIdx.x & 31;
    const int d0    = 2 * lane;
    const float scale = 0.125f;

    #pragma unroll
    for (int i = 0; i < 2; i++) {
        int idx = threadIdx.x + i * 256;
        int qr = idx >> 4, c4 = idx & 15;
        const float* qptr = qkv + (size_t)(b * T_SEQ + qbase + qr) * C3 + h * DHEAD + c4 * 4;
        *(float4*)&qsh[qr * 68 + c4 * 4] = *(const float4*)qptr;
    }

    const float* Kbase = qkv + (size_t)(b * T_SEQ) * C3 + CDIM     + h * DHEAD;
    const float* Vbase = qkv + (size_t)(b * T_SEQ) * C3 + 2 * CDIM + h * DHEAD;
    const int ntiles = (qbase >> 6) + 1;

    float denl[4], y0[4], y1[4];
    #pragma unroll
    for (int g = 0; g < 4; g++) { denl[g] = 0.f; y0[g] = 0.f; y1[g] = 0.f; }

    for (int tile = 0; tile < ntiles; tile++) {
        const int kt0 = tile << 6;
        __syncthreads();
        #pragma unroll
        for (int i = 0; i < 4; i++) {
            int idx = threadIdx.x + i * 256;
            int r = idx >> 4, c4 = idx & 15;
            size_t gofs = (size_t)(kt0 + r) * C3 + c4 * 4;
            int prow = (r & 1) ? (32 + (r >> 1)) : (r >> 1);
            *(float4*)&Ksh[prow * 68 + c4 * 4] = *(const float4*)&Kbase[gofs];
            *(float4*)&Vsh[r    * 68 + c4 * 4] = *(const float4*)&Vbase[gofs];
        }
        __syncthreads();

        float p0[4] = {0.f, 0.f, 0.f, 0.f}, p1[4] = {0.f, 0.f, 0.f, 0.f};
        {
            const float4* K0 = (const float4*)&Ksh[lane * 68];
            const float4* K1 = (const float4*)&Ksh[(lane + 32) * 68];
            #pragma unroll
            for (int d4 = 0; d4 < 16; d4++) {
                float4 k0 = K0[d4], k1 = K1[d4];
                #pragma unroll
                for (int g = 0; g < 4; g++) {
                    float4 qv = *(const float4*)&qsh[(w * 4 + g) * 68 + d4 * 4];
                    p0[g] += qv.x * k0.x + qv.y * k0.y + qv.z * k0.z + qv.w * k0.w;
                    p1[g] += qv.x * k1.x + qv.y * k1.y + qv.z * k1.z + qv.w * k1.w;
                }
            }
        }

        float alpha_g[4];
        #pragma unroll
        for (int g = 0; g < 4; g++) {
            const int q    = qbase + w * 4 + g;
            const int key0 = kt0 + 2 * lane;
            const bool v0 = (key0 <= q), v1 = (key0 + 1 <= q);
            const float P0 = p0[g] * scale;
            const float P1 = p1[g] * scale;
            const float s0 = v0 ? __fdividef(1.0f, 1.0f + __expf(-P0)) : 0.f;
            const float s1 = v1 ? __fdividef(1.0f, 1.0f + __expf(-P1)) : 0.f;

            float sp = s0 + s1;
            float sc = sp;
            #pragma unroll
            for (int off = 1; off < 32; off <<= 1) {
                float tv = __shfl_up_sync(0xffffffffu, sc, off);
                if (lane >= off) sc += tv;
            }
            const float tot  = __shfl_sync(0xffffffffu, sc, 31);
            const float excl = sc - sp;

            const float c0 = excl - tot - 8.0f;
            const float e0 = v0 ? __expf(P0 + c0)      : 0.f;
            const float e1 = v1 ? __expf(P1 + c0 + s0) : 0.f;
            const float al = __expf(-tot);
            denl[g] = denl[g] * al + e0 + e1;
            alpha_g[g] = al;
            *(float2*)&esh[(w * 4 + g) * 64 + 2 * lane] = make_float2(e0, e1);
        }
        __syncwarp();

        #pragma unroll
        for (int g = 0; g < 4; g++) { y0[g] *= alpha_g[g]; y1[g] *= alpha_g[g]; }
        #pragma unroll
        for (int k4 = 0; k4 < 16; k4++) {
            float2 v0 = *(const float2*)&Vsh[(k4 * 4 + 0) * 68 + d0];
            float2 v1 = *(const float2*)&Vsh[(k4 * 4 + 1) * 68 + d0];
            float2 v2 = *(const float2*)&Vsh[(k4 * 4 + 2) * 68 + d0];
            float2 v3 = *(const float2*)&Vsh[(k4 * 4 + 3) * 68 + d0];
            #pragma unroll
            for (int g = 0; g < 4; g++) {
                float4 ev = *(const float4*)&esh[(w * 4 + g) * 64 + k4 * 4];
                y0[g] += ev.x * v0.x + ev.y * v1.x + ev.z * v2.x + ev.w * v3.x;
                y1[g] += ev.x * v0.y + ev.y * v1.y + ev.z * v2.y + ev.w * v3.y;
            }
        }
        __syncwarp();
    }

    #pragma unroll
    for (int g = 0; g < 4; g++) {
        float dsum = denl[g];
        #pragma unroll
        for (int off = 16; off; off >>= 1)
            dsum += __shfl_xor_sync(0xffffffffu, dsum, off);
        const float inv = 1.0f / dsum;
        const int q = qbase + w * 4 + g;
        float* yp = yout + (size_t)(b * T_SEQ + q) * CDIM + h * DHEAD + d0;
        *(float2*)yp = make_float2(y0[g] * inv, y1[g] * inv);
    }
}

// ---------------------------------------------------------------------------
extern "C" void kernel_launch(void* const* d_in, const int* in_sizes, int n_in,
                              void* d_out, int out_size)
{
    const float* x = nullptr; const float* Wa = nullptr; const float* Wp = nullptr;
    for (int i = 0; i < n_in; i++) {
        if (in_sizes[i] == BATCH * T_SEQ * CDIM)  x  = (const float*)d_in[i];
        else if (in_sizes[i] == C3 * CDIM)        Wa = (const float*)d_in[i];
        else if (in_sizes[i] == CDIM * CDIM)      Wp = (const float*)d_in[i];
    }
    float* out = (float*)d_out;

    void* qkv_p = nullptr; void* y_p = nullptr;
    cudaGetSymbolAddress(&qkv_p, g_qkv);
    cudaGetSymbolAddress(&y_p,   g_y);
    float* qkv = (float*)qkv_p;
    float* y   = (float*)y_p;

    const int GEMM_SMEM = 2 * GS_BUF * 4;         // 66,560 B (2 CTAs/SM)
    const int ATTN_SMEM = ATTN_SMEM_FLOATS * 4;   // 51,712 B
    cudaFuncSetAttribute(gemm_tf32_kernel, cudaFuncAttributeMaxDynamicSharedMemorySize, GEMM_SMEM);
    cudaFuncSetAttribute(attn_kernel,      cudaFuncAttributeMaxDynamicSharedMemorySize, ATTN_SMEM);

    {   // qkv = x @ W_attn^T
        dim3 grid(C3 / 128, MROWS / 128);
        gemm_tf32_kernel<<<grid, 256, GEMM_SMEM>>>(x, Wa, qkv, MROWS, C3, CDIM);
    }
    {   // penalized attention
        dim3 grid(T_SEQ / 32, HEADS, BATCH);
        attn_kernel<<<grid, 256, ATTN_SMEM>>>(qkv, y);
    }
    {   // out = y @ W_proj^T
        dim3 grid(CDIM / 128, MROWS / 128);
        gemm_tf32_kernel<<<grid, 256, GEMM_SMEM>>>(y, Wp, out, MROWS, CDIM, CDIM);
    }
}